// round 13
// baseline (speedup 1.0000x reference)
#include <cuda_runtime.h>
#include <cstdint>
#include <math.h>

#define NN 50000
#define EE 800000
#define TOT (EE + NN)

// ---------------- device scratch (no allocations allowed) ----------------
__device__ __align__(16) float g_h1[NN * 128];   // layer-1 linear output
__device__ __align__(16) float g_as1[NN * 4];    // per-node attn src terms (4 heads)
__device__ __align__(16) float g_ad1[NN * 4];    // per-node attn dst terms
__device__ __align__(16) float g_h2[NN * 2];     // layer-2 linear output
__device__ float g_as2[NN];
__device__ float g_ad2[NN];
__device__ int g_deg[NN];
__device__ int g_rowptr[NN + 1];
__device__ int g_cursor[NN];
__device__ int g_csr[TOT];

__device__ __forceinline__ float lrelu(float x) { return x > 0.f ? x : 0.2f * x; }

__device__ __forceinline__ uint32_t f2tf32(float f) {
    uint32_t r;
    asm("cvt.rna.tf32.f32 %0, %1;" : "=r"(r) : "f"(f));
    return r;
}

// m16n8k8 tf32 MMA, D += A*B (row.col), fp32 accumulate
__device__ __forceinline__ void mma_tf32(float* c, const uint32_t* a, const uint32_t* b) {
    asm volatile(
        "mma.sync.aligned.m16n8k8.row.col.f32.tf32.tf32.f32 "
        "{%0,%1,%2,%3}, {%4,%5,%6,%7}, {%8,%9}, {%0,%1,%2,%3};\n"
        : "+f"(c[0]), "+f"(c[1]), "+f"(c[2]), "+f"(c[3])
        : "r"(a[0]), "r"(a[1]), "r"(a[2]), "r"(a[3]), "r"(b[0]), "r"(b[1]));
}

// ---------------- CSR build ----------------
__global__ void k_zero_deg() {
    int i = blockIdx.x * blockDim.x + threadIdx.x;
    if (i < NN) g_deg[i] = 0;
}

__global__ void k_hist(const int* __restrict__ ei) {
    int i = blockIdx.x * blockDim.x + threadIdx.x;
    if (i < EE) {
        atomicAdd(&g_deg[ei[EE + i]], 1);
    } else if (i < TOT) {
        atomicAdd(&g_deg[i - EE], 1);
    }
}

__global__ void k_scan() {
    __shared__ int part[1024];
    int t = threadIdx.x;
    const int C = (NN + 1023) / 1024;
    int lo = t * C;
    int hi = lo + C;
    if (hi > NN) hi = NN;
    int s = 0;
    for (int i = lo; i < hi; i++) s += g_deg[i];
    part[t] = s;
    __syncthreads();
    for (int off = 1; off < 1024; off <<= 1) {
        int v = (t >= off) ? part[t - off] : 0;
        __syncthreads();
        part[t] += v;
        __syncthreads();
    }
    int run = (t > 0) ? part[t - 1] : 0;
    for (int i = lo; i < hi; i++) {
        g_rowptr[i] = run;
        g_cursor[i] = run;
        run += g_deg[i];
    }
    if (t == 1023) g_rowptr[NN] = part[1023];
}

__global__ void k_scatter(const int* __restrict__ ei) {
    int i = blockIdx.x * blockDim.x + threadIdx.x;
    if (i < EE) {
        int src = ei[i];
        int dst = ei[EE + i];
        int pos = atomicAdd(&g_cursor[dst], 1);
        g_csr[pos] = src;
    } else if (i < TOT) {
        int v = i - EE;
        int pos = atomicAdd(&g_cursor[v], 1);
        g_csr[pos] = v;
    }
}

// ---------------- GEMM1 via mma.sync tf32 (3xTF32) + fused attn terms -------
// CTA = 64 rows x 128 cols, 256 threads (8 warps), warp tile 32m x 32n.
// 3xTF32: acc += Ahi*Bhi + Ahi*Blo + Alo*Bhi  -> ~fp32 accuracy.
// Warp's 32 cols == one head, so as1/ad1 dots reduce over 4 lanes only.
// A-fragment order (PTX): a0=(r,c) a1=(r+8,c) a2=(r,c+4) a3=(r+8,c+4).
// smem floats:
//   A_hi [64][132]  @ 0        (8448)
//   A_lo [64][132]  @ 8448     (8448)
//   B_hi [128][136] @ 16896    (17408)   B[k][n] = W1[k][n]
//   B_lo [128][136] @ 34304    (17408)
#define A_ST 132
#define B_ST 136
#define OFF_ALO 8448
#define OFF_BHI 16896
#define OFF_BLO 34304
#define GEMM_SMEM ((34304 + 17408) * 4)

__global__ void __launch_bounds__(256) k_gemm1_mma(
    const float* __restrict__ x, const float* __restrict__ W,
    const float* __restrict__ asrc, const float* __restrict__ adst) {
    extern __shared__ float sm[];
    uint32_t* Ahi = (uint32_t*)sm;
    uint32_t* Alo = (uint32_t*)(sm + OFF_ALO);
    uint32_t* Bhi = (uint32_t*)(sm + OFF_BHI);
    uint32_t* Blo = (uint32_t*)(sm + OFF_BLO);
    int tid = threadIdx.x;
    int row0 = blockIdx.x * 64;

    // fill A tiles: 64 rows x 32 float4
    for (int i = tid; i < 2048; i += 256) {
        int r = i >> 5, c = (i & 31) * 4;
        float4 v;
        if (row0 + r < NN) v = ((const float4*)x)[(row0 + r) * 32 + (i & 31)];
        else v = make_float4(0.f, 0.f, 0.f, 0.f);
        float* vp = &v.x;
#pragma unroll
        for (int j = 0; j < 4; j++) {
            uint32_t hb = f2tf32(vp[j]);
            float lo = vp[j] - __uint_as_float(hb);
            Ahi[r * A_ST + c + j] = hb;
            Alo[r * A_ST + c + j] = f2tf32(lo);
        }
    }
    // fill B tiles: W1 [128k x 128n], 4096 float4
    for (int i = tid; i < 4096; i += 256) {
        int k = i >> 5, n = (i & 31) * 4;
        float4 v = ((const float4*)W)[i];
        float* vp = &v.x;
#pragma unroll
        for (int j = 0; j < 4; j++) {
            uint32_t hb = f2tf32(vp[j]);
            float lo = vp[j] - __uint_as_float(hb);
            Bhi[k * B_ST + n + j] = hb;
            Blo[k * B_ST + n + j] = f2tf32(lo);
        }
    }
    __syncthreads();

    int w = tid >> 5, lane = tid & 31;
    int wm = w & 1, wn = w >> 1;             // warp rows [wm*32,+32), cols [wn*32,+32)
    int l4 = lane >> 2, lq = lane & 3;

    float acc[2][4][4];
#pragma unroll
    for (int t = 0; t < 2; t++)
#pragma unroll
        for (int u = 0; u < 4; u++)
#pragma unroll
            for (int q = 0; q < 4; q++) acc[t][u][q] = 0.f;

#pragma unroll
    for (int kk = 0; kk < 16; kk++) {
        int k0 = kk * 8;
        uint32_t ah[2][4], al[2][4], bh[4][2], bl[4][2];
#pragma unroll
        for (int t = 0; t < 2; t++) {
            int rb = (wm * 32 + t * 16 + l4) * A_ST + k0 + lq;
            ah[t][0] = Ahi[rb];                     // (r,      c)
            ah[t][1] = Ahi[rb + 8 * A_ST];          // (r+8,    c)
            ah[t][2] = Ahi[rb + 4];                 // (r,      c+4)
            ah[t][3] = Ahi[rb + 8 * A_ST + 4];      // (r+8,    c+4)
            al[t][0] = Alo[rb];
            al[t][1] = Alo[rb + 8 * A_ST];
            al[t][2] = Alo[rb + 4];
            al[t][3] = Alo[rb + 8 * A_ST + 4];
        }
#pragma unroll
        for (int u = 0; u < 4; u++) {
            int nb = (k0 + lq) * B_ST + wn * 32 + u * 8 + l4;
            bh[u][0] = Bhi[nb];                     // (k,   n)
            bh[u][1] = Bhi[nb + 4 * B_ST];          // (k+4, n)
            bl[u][0] = Blo[nb];
            bl[u][1] = Blo[nb + 4 * B_ST];
        }
#pragma unroll
        for (int t = 0; t < 2; t++)
#pragma unroll
            for (int u = 0; u < 4; u++) {
                mma_tf32(acc[t][u], ah[t], bh[u]);
                mma_tf32(acc[t][u], ah[t], bl[u]);
                mma_tf32(acc[t][u], al[t], bh[u]);
            }
    }

    // epilogue: store h1 + fused head-dot attn terms (head == wn)
    float sa[2][2] = {{0.f, 0.f}, {0.f, 0.f}};   // [t][row-half]
    float sd[2][2] = {{0.f, 0.f}, {0.f, 0.f}};
#pragma unroll
    for (int t = 0; t < 2; t++) {
        int rg = row0 + wm * 32 + t * 16 + l4;
#pragma unroll
        for (int u = 0; u < 4; u++) {
            int col = wn * 32 + u * 8 + 2 * lq;
            float c0 = acc[t][u][0], c1 = acc[t][u][1];
            float c2 = acc[t][u][2], c3 = acc[t][u][3];
            if (rg < NN)
                *(float2*)&g_h1[rg * 128 + col] = make_float2(c0, c1);
            if (rg + 8 < NN)
                *(float2*)&g_h1[(rg + 8) * 128 + col] = make_float2(c2, c3);
            float a0 = __ldg(&asrc[col]), a1 = __ldg(&asrc[col + 1]);
            float d0 = __ldg(&adst[col]), d1 = __ldg(&adst[col + 1]);
            sa[t][0] += c0 * a0 + c1 * a1;
            sa[t][1] += c2 * a0 + c3 * a1;
            sd[t][0] += c0 * d0 + c1 * d1;
            sd[t][1] += c2 * d0 + c3 * d1;
        }
    }
    // reduce over the 4 lanes sharing a row (lane bits 0,1)
#pragma unroll
    for (int t = 0; t < 2; t++)
#pragma unroll
        for (int hlf = 0; hlf < 2; hlf++) {
            sa[t][hlf] += __shfl_xor_sync(0xffffffffu, sa[t][hlf], 1);
            sa[t][hlf] += __shfl_xor_sync(0xffffffffu, sa[t][hlf], 2);
            sd[t][hlf] += __shfl_xor_sync(0xffffffffu, sd[t][hlf], 1);
            sd[t][hlf] += __shfl_xor_sync(0xffffffffu, sd[t][hlf], 2);
        }
    if (lq == 0) {
#pragma unroll
        for (int t = 0; t < 2; t++) {
            int rg = row0 + wm * 32 + t * 16 + l4;
            if (rg < NN) {
                g_as1[rg * 4 + wn] = sa[t][0];
                g_ad1[rg * 4 + wn] = sd[t][0];
            }
            if (rg + 8 < NN) {
                g_as1[(rg + 8) * 4 + wn] = sa[t][1];
                g_ad1[(rg + 8) * 4 + wn] = sd[t][1];
            }
        }
    }
}

// ---------------- layer-1 softmax agg + relu + layer-2 linear (warp/dst) ----
__global__ void k_agg1(const float* __restrict__ b1,
                       const float* __restrict__ W2,
                       const float* __restrict__ asrc2,
                       const float* __restrict__ adst2) {
    int g = blockIdx.x * blockDim.x + threadIdx.x;
    int n = g >> 5, lane = g & 31;
    if (n >= NN) return;
    int beg = g_rowptr[n], end = g_rowptr[n + 1];
    float4 ad = *(const float4*)&g_ad1[n * 4];

    float m0 = -1e30f, m1 = -1e30f, m2 = -1e30f, m3 = -1e30f;
    for (int j = beg + lane; j < end; j += 32) {
        int s = g_csr[j];
        float4 avv = *(const float4*)&g_as1[s * 4];
        m0 = fmaxf(m0, lrelu(avv.x + ad.x));
        m1 = fmaxf(m1, lrelu(avv.y + ad.y));
        m2 = fmaxf(m2, lrelu(avv.z + ad.z));
        m3 = fmaxf(m3, lrelu(avv.w + ad.w));
    }
#pragma unroll
    for (int off = 16; off; off >>= 1) {
        m0 = fmaxf(m0, __shfl_xor_sync(0xffffffffu, m0, off));
        m1 = fmaxf(m1, __shfl_xor_sync(0xffffffffu, m1, off));
        m2 = fmaxf(m2, __shfl_xor_sync(0xffffffffu, m2, off));
        m3 = fmaxf(m3, __shfl_xor_sync(0xffffffffu, m3, off));
    }

    float a0 = 0.f, a1 = 0.f, a2 = 0.f, a3 = 0.f;
    float d0 = 0.f, d1 = 0.f, d2 = 0.f, d3 = 0.f;
    for (int j = beg; j < end; j++) {
        int s = g_csr[j];
        float4 avv = *(const float4*)&g_as1[s * 4];
        float p0 = __expf(lrelu(avv.x + ad.x) - m0);
        float p1 = __expf(lrelu(avv.y + ad.y) - m1);
        float p2 = __expf(lrelu(avv.z + ad.z) - m2);
        float p3 = __expf(lrelu(avv.w + ad.w) - m3);
        const float* hr = &g_h1[s * 128];
        a0 = fmaf(p0, hr[lane], a0);
        a1 = fmaf(p1, hr[32 + lane], a1);
        a2 = fmaf(p2, hr[64 + lane], a2);
        a3 = fmaf(p3, hr[96 + lane], a3);
        d0 += p0; d1 += p1; d2 += p2; d3 += p3;
    }
    float o0 = fmaxf(a0 / (d0 + 1e-16f) + __ldg(&b1[lane]), 0.f);
    float o1 = fmaxf(a1 / (d1 + 1e-16f) + __ldg(&b1[32 + lane]), 0.f);
    float o2 = fmaxf(a2 / (d2 + 1e-16f) + __ldg(&b1[64 + lane]), 0.f);
    float o3 = fmaxf(a3 / (d3 + 1e-16f) + __ldg(&b1[96 + lane]), 0.f);

    float c0 = o0 * __ldg(&W2[lane * 2])            + o1 * __ldg(&W2[(32 + lane) * 2])
             + o2 * __ldg(&W2[(64 + lane) * 2])     + o3 * __ldg(&W2[(96 + lane) * 2]);
    float c1 = o0 * __ldg(&W2[lane * 2 + 1])        + o1 * __ldg(&W2[(32 + lane) * 2 + 1])
             + o2 * __ldg(&W2[(64 + lane) * 2 + 1]) + o3 * __ldg(&W2[(96 + lane) * 2 + 1]);
#pragma unroll
    for (int off = 16; off; off >>= 1) {
        c0 += __shfl_xor_sync(0xffffffffu, c0, off);
        c1 += __shfl_xor_sync(0xffffffffu, c1, off);
    }
    if (lane == 0) {
        g_h2[2 * n]     = c0;
        g_h2[2 * n + 1] = c1;
        g_as2[n] = c0 * __ldg(&asrc2[0]) + c1 * __ldg(&asrc2[1]);
        g_ad2[n] = c0 * __ldg(&adst2[0]) + c1 * __ldg(&adst2[1]);
    }
}

// ---------------- layer-2 aggregation + log_softmax (warp per dst) ----------
__global__ void k_agg2(const float* __restrict__ b2, float* __restrict__ out) {
    int g = blockIdx.x * blockDim.x + threadIdx.x;
    int n = g >> 5, lane = g & 31;
    if (n >= NN) return;
    int beg = g_rowptr[n], end = g_rowptr[n + 1];
    float adv = g_ad2[n];

    float m = -1e30f;
    for (int j = beg + lane; j < end; j += 32)
        m = fmaxf(m, lrelu(g_as2[g_csr[j]] + adv));
#pragma unroll
    for (int off = 16; off; off >>= 1)
        m = fmaxf(m, __shfl_xor_sync(0xffffffffu, m, off));

    float a0 = 0.f, a1 = 0.f, den = 0.f;
    for (int j = beg + lane; j < end; j += 32) {
        int s = g_csr[j];
        float p = __expf(lrelu(g_as2[s] + adv) - m);
        float2 hv = *(const float2*)&g_h2[2 * s];
        a0 = fmaf(p, hv.x, a0);
        a1 = fmaf(p, hv.y, a1);
        den += p;
    }
#pragma unroll
    for (int off = 16; off; off >>= 1) {
        a0 += __shfl_xor_sync(0xffffffffu, a0, off);
        a1 += __shfl_xor_sync(0xffffffffu, a1, off);
        den += __shfl_xor_sync(0xffffffffu, den, off);
    }
    if (lane == 0) {
        float o0 = a0 / (den + 1e-16f) + b2[0];
        float o1 = a1 / (den + 1e-16f) + b2[1];
        float mm = fmaxf(o0, o1);
        float lse = mm + logf(expf(o0 - mm) + expf(o1 - mm));
        out[2 * n]     = o0 - lse;
        out[2 * n + 1] = o1 - lse;
    }
}

// ---------------- launch ----------------
extern "C" void kernel_launch(void* const* d_in, const int* in_sizes, int n_in,
                              void* d_out, int out_size) {
    (void)in_sizes; (void)n_in; (void)out_size;
    const float* x     = (const float*)d_in[0];
    const int*   ei    = (const int*)d_in[1];
    const float* W1    = (const float*)d_in[2];
    const float* asrc1 = (const float*)d_in[3];
    const float* adst1 = (const float*)d_in[4];
    const float* b1    = (const float*)d_in[5];
    const float* W2    = (const float*)d_in[6];
    const float* asrc2 = (const float*)d_in[7];
    const float* adst2 = (const float*)d_in[8];
    const float* b2    = (const float*)d_in[9];
    float* out = (float*)d_out;

    cudaFuncSetAttribute(k_gemm1_mma, cudaFuncAttributeMaxDynamicSharedMemorySize,
                         GEMM_SMEM);

    // CSR build
    k_zero_deg<<<(NN + 255) / 256, 256>>>();
    k_hist<<<(TOT + 255) / 256, 256>>>(ei);
    k_scan<<<1, 1024>>>();
    k_scatter<<<(TOT + 255) / 256, 256>>>(ei);

    // layer 1 linear (tensor-core tf32 3x) + fused attn terms
    k_gemm1_mma<<<(NN + 63) / 64, 256, GEMM_SMEM>>>(x, W1, asrc1, adst1);
    // layer-1 softmax agg + relu + layer-2 linear fused
    k_agg1<<<(NN * 32 + 255) / 256, 256>>>(b1, W2, asrc2, adst2);
    // layer-2 aggregation + log_softmax
    k_agg2<<<(NN * 32 + 255) / 256, 256>>>(b2, out);
}